// round 1
// baseline (speedup 1.0000x reference)
#include <cuda_runtime.h>
#include <math.h>
#include <stdint.h>

// Problem constants (shape-fixed per reference: N=8192, D=512, 3 classes)
#define NMAX 8192
#define DMAX 512

// ---------------- device scratch (static, no runtime allocation) ------------
__device__ float g_fn[(size_t)NMAX * DMAX];          // normalized features, 16 MB
__device__ float g_S[(size_t)NMAX * NMAX];           // scaled logits, 256 MB
__device__ signed char g_code[NMAX];                 // valid ? label(0..2) : 3
__device__ float g_neglse[NMAX];                     // per-anchor logsumexp over negatives
__device__ float g_rowloss[NMAX];
__device__ int   g_rowflag[NMAX];                    // processed && has_pos

// ---------------- kernel 1: normalize rows + build code ---------------------
__global__ void __launch_bounds__(128) k_normalize(
    const float* __restrict__ feats,
    const int* __restrict__ labels,
    const int* __restrict__ bad,
    int N, int D)
{
    int i = blockIdx.x;
    int tid = threadIdx.x;
    const float* x = feats + (size_t)i * D;

    float ss = 0.f;
    for (int k = tid; k < D; k += 128) {
        float v = x[k];
        ss += v * v;
    }
    __shared__ float red[128];
    red[tid] = ss;
    __syncthreads();
    for (int off = 64; off > 0; off >>= 1) {
        if (tid < off) red[tid] += red[tid + off];
        __syncthreads();
    }
    float rinv = 1.f / sqrtf(red[0]);

    float* y = g_fn + (size_t)i * D;
    for (int k = tid; k < D; k += 128) {
        y[k] = x[k] * rinv;
    }
    if (tid == 0) {
        g_code[i] = (bad[i] == 0) ? (signed char)labels[i] : (signed char)3;
    }
}

// ---------------- kernel 2: SGEMM  S = (fn @ fn^T) * 10 ---------------------
#define BM 128
#define BN 128
#define BK 16
#define PAD 4

__global__ void __launch_bounds__(256) k_sgemm(int N, int D)
{
    __shared__ float As[BK][BM + PAD];
    __shared__ float Bs[BK][BN + PAD];

    const int tid = threadIdx.x;
    const int tx = tid & 15;
    const int ty = tid >> 4;
    const int row0 = blockIdx.y * BM;
    const int col0 = blockIdx.x * BN;

    float acc[8][8];
#pragma unroll
    for (int m = 0; m < 8; m++)
#pragma unroll
        for (int n = 0; n < 8; n++) acc[m][n] = 0.f;

    const float* __restrict__ fn = g_fn;

    for (int k0 = 0; k0 < D; k0 += BK) {
#pragma unroll
        for (int i = 0; i < 8; i++) {
            int e = tid + i * 256;        // 2048 elements per tile
            int r = e >> 4;
            int c = e & 15;
            As[c][r] = fn[(size_t)(row0 + r) * D + k0 + c];
            Bs[c][r] = fn[(size_t)(col0 + r) * D + k0 + c];
        }
        __syncthreads();

#pragma unroll
        for (int k = 0; k < BK; k++) {
            float a[8], b[8];
#pragma unroll
            for (int m = 0; m < 4; m++) {
                a[m]     = As[k][ty * 4 + m];
                a[4 + m] = As[k][64 + ty * 4 + m];
            }
#pragma unroll
            for (int n = 0; n < 4; n++) {
                b[n]     = Bs[k][tx * 4 + n];
                b[4 + n] = Bs[k][64 + tx * 4 + n];
            }
#pragma unroll
            for (int m = 0; m < 8; m++)
#pragma unroll
                for (int n = 0; n < 8; n++)
                    acc[m][n] += a[m] * b[n];
        }
        __syncthreads();
    }

    // write back, scaled by 1/TEMPERATURE (0.1f) to match reference exactly
    const float invT = 1.0f / 0.1f;
    float* __restrict__ S = g_S;
#pragma unroll
    for (int m = 0; m < 8; m++) {
        int r = row0 + ((m < 4) ? (ty * 4 + m) : (64 + ty * 4 + (m - 4)));
        float4 v0 = make_float4(acc[m][0] * invT, acc[m][1] * invT,
                                acc[m][2] * invT, acc[m][3] * invT);
        float4 v1 = make_float4(acc[m][4] * invT, acc[m][5] * invT,
                                acc[m][6] * invT, acc[m][7] * invT);
        *reinterpret_cast<float4*>(&S[(size_t)r * N + col0 + tx * 4]) = v0;
        *reinterpret_cast<float4*>(&S[(size_t)r * N + col0 + 64 + tx * 4]) = v1;
    }
}

// ---------------- kernel 3: per-row logsumexp over negatives ----------------
__global__ void __launch_bounds__(256) k_neglse(
    const int* __restrict__ labels, int N)
{
    int i = blockIdx.x;
    int tid = threadIdx.x;
    int lab = labels[i];
    const float* __restrict__ row = g_S + (size_t)i * N;

    float m = -INFINITY;
    float s = 0.f;
    for (int j = tid; j < N; j += 256) {
        int c = g_code[j];
        if (c != 3 && c != lab) {
            float v = row[j];
            if (v > m) {
                s = s * expf(m - v) + 1.f;   // expf(-inf) == 0, safe
                m = v;
            } else {
                s += expf(v - m);
            }
        }
    }

    __shared__ float sm_m[256];
    __shared__ float sm_s[256];
    sm_m[tid] = m;
    sm_s[tid] = s;
    __syncthreads();
    for (int off = 128; off > 0; off >>= 1) {
        if (tid < off) {
            float m2 = sm_m[tid + off], s2 = sm_s[tid + off];
            float m1 = sm_m[tid],       s1 = sm_s[tid];
            if (s2 > 0.f) {
                if (s1 <= 0.f)      { m1 = m2; s1 = s2; }
                else if (m2 <= m1)  { s1 += s2 * expf(m2 - m1); }
                else                { s1 = s1 * expf(m1 - m2) + s2; m1 = m2; }
            }
            sm_m[tid] = m1;
            sm_s[tid] = s1;
        }
        __syncthreads();
    }
    if (tid == 0) {
        g_neglse[i] = (sm_s[0] > 0.f) ? (sm_m[0] + logf(sm_s[0])) : -1e30f;
    }
}

// ---------------- kernel 4: per-row positive CE + anchor loss ----------------
__device__ __forceinline__ float log1pexp(float d) {
    // log(1 + exp(d)), stable
    return (d > 0.f) ? (d + log1pf(expf(-d))) : log1pf(expf(d));
}

__global__ void __launch_bounds__(256) k_posloss(
    const int* __restrict__ labels, int N)
{
    int i = blockIdx.x;
    int tid = threadIdx.x;
    int lab = labels[i];
    float L = g_neglse[i];
    const float* __restrict__ row = g_S + (size_t)i * N;

    float sum = 0.f;
    int cnt = 0;
    for (int j = tid; j < N; j += 256) {
        // g_code[j] == lab implies j valid (invalid coded as 3, labels are 0..2)
        if (g_code[j] == lab && j != i) {
            float sij = row[j];
            sum += log1pexp(L - sij);    // logaddexp(S, L) - S
            cnt++;
        }
    }

    __shared__ float ssum[256];
    __shared__ int   scnt[256];
    ssum[tid] = sum;
    scnt[tid] = cnt;
    __syncthreads();
    for (int off = 128; off > 0; off >>= 1) {
        if (tid < off) {
            ssum[tid] += ssum[tid + off];
            scnt[tid] += scnt[tid + off];
        }
        __syncthreads();
    }

    if (tid == 0) {
        bool valid_i   = (g_code[i] != 3);
        bool has_neg   = (L > -1e29f);
        bool processed = valid_i && has_neg;
        bool has_pos   = (scnt[0] > 0);
        float loss;
        if (has_pos) {
            loss = ssum[0] / (float)scnt[0];
        } else {
            const float invT = 1.0f / 0.1f;
            loss = log1pexp(L - invT);   // logaddexp(invT, L) - invT
        }
        g_rowloss[i] = processed ? loss : 0.f;
        g_rowflag[i] = (processed && has_pos) ? 1 : 0;
    }
}

// ---------------- kernel 5: final deterministic reduction -------------------
__global__ void __launch_bounds__(256) k_finalize(float* __restrict__ out, int N)
{
    int tid = threadIdx.x;
    float s = 0.f;
    int c = 0;
    for (int j = tid; j < N; j += 256) {
        s += g_rowloss[j];
        c += g_rowflag[j];
    }
    __shared__ float ssum[256];
    __shared__ int   scnt[256];
    ssum[tid] = s;
    scnt[tid] = c;
    __syncthreads();
    for (int off = 128; off > 0; off >>= 1) {
        if (tid < off) {
            ssum[tid] += ssum[tid + off];
            scnt[tid] += scnt[tid + off];
        }
        __syncthreads();
    }
    if (tid == 0) {
        out[0] = ssum[0] / (float)(1 + scnt[0]);
    }
}

// ---------------- launcher ---------------------------------------------------
extern "C" void kernel_launch(void* const* d_in, const int* in_sizes, int n_in,
                              void* d_out, int out_size)
{
    const float* feats  = (const float*)d_in[0];
    const int*   labels = (const int*)d_in[1];
    const int*   bad    = (const int*)d_in[2];
    float* out = (float*)d_out;

    const int N = in_sizes[1];            // 8192
    const int D = in_sizes[0] / N;        // 512

    k_normalize<<<N, 128>>>(feats, labels, bad, N, D);

    dim3 grid(N / BN, N / BM);
    k_sgemm<<<grid, 256>>>(N, D);

    k_neglse<<<N, 256>>>(labels, N);
    k_posloss<<<N, 256>>>(labels, N);
    k_finalize<<<1, 256>>>(out, N);
}

// round 2
// speedup vs baseline: 3.7597x; 3.7597x over previous
#include <cuda_runtime.h>
#include <math.h>
#include <stdint.h>

// Shapes fixed by the problem: N=8192, D=512, 3 classes
#define NMAX 8192
#define DMAX 512

// ---------------- device scratch (static, no runtime allocation) ------------
__device__ float g_fn[(size_t)NMAX * DMAX];          // normalized features (16 MB)
__device__ float g_S[(size_t)NMAX * NMAX];           // scaled logits (256 MB)
__device__ signed char g_code[NMAX];                 // valid ? label(0..2) : 3
__device__ float g_rowloss[NMAX];
__device__ int   g_rowflag[NMAX];

// ---------------- helpers ----------------------------------------------------
__device__ __forceinline__ float tf32r(float x) {
    uint32_t u;
    asm("cvt.rna.tf32.f32 %0, %1;" : "=r"(u) : "f"(x));
    return __uint_as_float(u);
}

__device__ __forceinline__ float wred_f(float x) {
#pragma unroll
    for (int o = 16; o; o >>= 1) x += __shfl_xor_sync(0xffffffffu, x, o);
    return x;
}
__device__ __forceinline__ int wred_i(int x) {
#pragma unroll
    for (int o = 16; o; o >>= 1) x += __shfl_xor_sync(0xffffffffu, x, o);
    return x;
}

__device__ __forceinline__ void mma_tf32(float* d, const uint32_t* a, const uint32_t* b) {
    asm volatile(
        "mma.sync.aligned.m16n8k8.row.col.f32.tf32.tf32.f32 "
        "{%0,%1,%2,%3}, {%4,%5,%6,%7}, {%8,%9}, {%0,%1,%2,%3};"
        : "+f"(d[0]), "+f"(d[1]), "+f"(d[2]), "+f"(d[3])
        : "r"(a[0]), "r"(a[1]), "r"(a[2]), "r"(a[3]),
          "r"(b[0]), "r"(b[1]));
}

// ---------------- kernel 1: normalize rows + build code ---------------------
__global__ void __launch_bounds__(128) k_normalize(
    const float* __restrict__ feats,
    const int* __restrict__ labels,
    const int* __restrict__ bad,
    int N, int D)
{
    const int i = blockIdx.x;
    const int tid = threadIdx.x;
    float4 v = reinterpret_cast<const float4*>(feats + (size_t)i * D)[tid];
    float ss = v.x * v.x + v.y * v.y + v.z * v.z + v.w * v.w;
    ss = wred_f(ss);
    __shared__ float w[4];
    if ((tid & 31) == 0) w[tid >> 5] = ss;
    __syncthreads();
    float tot = w[0] + w[1] + w[2] + w[3];
    float rinv = rsqrtf(tot);
    float4 o4 = make_float4(v.x * rinv, v.y * rinv, v.z * rinv, v.w * rinv);
    reinterpret_cast<float4*>(g_fn + (size_t)i * D)[tid] = o4;
    if (tid == 0) {
        g_code[i] = (bad[i] == 0) ? (signed char)labels[i] : (signed char)3;
    }
}

// ---------------- kernel 2: tf32 tensor-core GEMM  S = (fn fn^T) * 10 -------
// 128x128 block tile, BK=32 (4 k-steps of 8). 256 threads = 8 warps (2m x 4n),
// warp tile 64x32 -> 4x4 mma(m16n8k8) tiles, 64 fp32 accumulators/thread.
// Smem holds pre-permuted mma fragments (XOR-swizzled), so compute-side loads
// are LDS.128 / LDS.64.
__global__ void __launch_bounds__(256) k_gemm_tf32(int N, int D)
{
    __shared__ float Asm[4096];   // [ks][mt(8)][lane(32)^swz][reg(4)]
    __shared__ float Bsm[4096];   // [ks][nt(16)][lane(32)^swz][reg(2)]

    const int tid  = threadIdx.x;
    const int lane = tid & 31;
    const int warp = tid >> 5;
    const int wm   = warp >> 2;       // 0..1
    const int wn   = warp & 3;        // 0..3
    const int row0 = blockIdx.y * 128;
    const int col0 = blockIdx.x * 128;

    const int lr = tid >> 3;          // 0..31  (row within tile, x4)
    const int lc = (tid & 7) << 2;    // 0..28  (col group of 4)

    const float* __restrict__ fn = g_fn;

    float acc[4][4][4];
#pragma unroll
    for (int a = 0; a < 4; a++)
#pragma unroll
        for (int b = 0; b < 4; b++)
#pragma unroll
            for (int c = 0; c < 4; c++) acc[a][b][c] = 0.f;

    // prefetch first tile
    float4 a4[4], b4[4];
#pragma unroll
    for (int r = 0; r < 4; r++) {
        a4[r] = *reinterpret_cast<const float4*>(fn + (size_t)(row0 + lr + 32 * r) * D + lc);
        b4[r] = *reinterpret_cast<const float4*>(fn + (size_t)(col0 + lr + 32 * r) * D + lc);
    }

    for (int k0 = 0; k0 < D; k0 += 32) {
        __syncthreads();   // previous compute done reading smem

        // scatter current tile into fragment-permuted smem (tf32-rounded)
#pragma unroll
        for (int r = 0; r < 4; r++) {
            const float av[4] = {a4[r].x, a4[r].y, a4[r].z, a4[r].w};
            const float bv[4] = {b4[r].x, b4[r].y, b4[r].z, b4[r].w};
            const int m  = lr + 32 * r;     // row for A, col(n) for B
            const int mt = m >> 4, rr = m & 15;
            const int nt = m >> 3, cc = m & 7;
#pragma unroll
            for (int c = 0; c < 4; c++) {
                const int kc = lc + c;
                const int ks = kc >> 3, k7 = kc & 7;
                const int swz = 5 * ks;
                const int laneA = ((((rr & 7) << 2) | (k7 & 3)) ^ swz);
                const int regA  = (rr >> 3) | ((k7 >> 2) << 1);
                Asm[(((ks << 3) + mt) << 7) + (laneA << 2) + regA] = tf32r(av[c]);
                const int laneB = (((cc << 2) | (k7 & 3)) ^ swz);
                const int regB  = k7 >> 2;
                Bsm[(((ks << 4) + nt) << 6) + (laneB << 1) + regB] = tf32r(bv[c]);
            }
        }
        __syncthreads();

        // prefetch next tile while computing this one
        if (k0 + 32 < D) {
#pragma unroll
            for (int r = 0; r < 4; r++) {
                a4[r] = *reinterpret_cast<const float4*>(fn + (size_t)(row0 + lr + 32 * r) * D + lc + k0 + 32);
                b4[r] = *reinterpret_cast<const float4*>(fn + (size_t)(col0 + lr + 32 * r) * D + lc + k0 + 32);
            }
        }

        // compute 4 k-steps
#pragma unroll
        for (int ks = 0; ks < 4; ks++) {
            const int lsw = lane ^ (5 * ks);
            uint32_t A[4][4];
#pragma unroll
            for (int mt_ = 0; mt_ < 4; mt_++) {
                const int mt = (wm << 2) + mt_;
                float4 v = *reinterpret_cast<const float4*>(&Asm[(((ks << 3) + mt) << 7) + (lsw << 2)]);
                A[mt_][0] = __float_as_uint(v.x);
                A[mt_][1] = __float_as_uint(v.y);
                A[mt_][2] = __float_as_uint(v.z);
                A[mt_][3] = __float_as_uint(v.w);
            }
            uint32_t B[4][2];
#pragma unroll
            for (int nt_ = 0; nt_ < 4; nt_++) {
                const int nt = (wn << 2) + nt_;
                float2 v = *reinterpret_cast<const float2*>(&Bsm[(((ks << 4) + nt) << 6) + (lsw << 1)]);
                B[nt_][0] = __float_as_uint(v.x);
                B[nt_][1] = __float_as_uint(v.y);
            }
#pragma unroll
            for (int mt_ = 0; mt_ < 4; mt_++)
#pragma unroll
                for (int nt_ = 0; nt_ < 4; nt_++)
                    mma_tf32(acc[mt_][nt_], A[mt_], B[nt_]);
        }
    }

    // epilogue: scale by 1/T = 10 and store
    const float invT = 10.f;
    const int g = lane >> 2;
    const int t = lane & 3;
    float* __restrict__ S = g_S;
#pragma unroll
    for (int mt_ = 0; mt_ < 4; mt_++) {
        const int row = row0 + (wm << 6) + (mt_ << 4) + g;
#pragma unroll
        for (int nt_ = 0; nt_ < 4; nt_++) {
            const int col = col0 + (wn << 5) + (nt_ << 3) + (t << 1);
            float2 lo = make_float2(acc[mt_][nt_][0] * invT, acc[mt_][nt_][1] * invT);
            float2 hi = make_float2(acc[mt_][nt_][2] * invT, acc[mt_][nt_][3] * invT);
            *reinterpret_cast<float2*>(&S[(size_t)row * N + col]) = lo;
            *reinterpret_cast<float2*>(&S[(size_t)(row + 8) * N + col]) = hi;
        }
    }
}

// ---------------- kernel 3: fused per-row loss (neg-lse + pos CE) ------------
// One block per anchor row. Invalid anchors exit immediately (processed=false).
// Row cached in smem; pass1 computes negative-sum(exp(s-10)) + positive count,
// pass2 computes the positive CE sum. All reductions fixed-order.
__global__ void __launch_bounds__(256) k_rowloss(int N)
{
    __shared__ float srow[NMAX];
    __shared__ signed char scode[NMAX];
    __shared__ float redf[8];
    __shared__ int   redi[8];
    __shared__ float sL;
    __shared__ int   sP;

    const int i = blockIdx.x;
    const int tid = threadIdx.x;

    const int ci = g_code[i];
    if (ci == 3) {                       // invalid anchor: not processed
        if (tid == 0) { g_rowloss[i] = 0.f; g_rowflag[i] = 0; }
        return;
    }
    const int lab = ci;

    const float4* __restrict__ rv = reinterpret_cast<const float4*>(g_S + (size_t)i * N);
    const char4*  __restrict__ cv = reinterpret_cast<const char4*>(g_code);
    float4* sr4 = reinterpret_cast<float4*>(srow);
    char4*  sc4 = reinterpret_cast<char4*>(scode);

    // pass 1: neg-sum of exp(s - 10) + positive count (also fills smem caches)
    float negsum = 0.f;
    int   pcnt   = 0;
    const int nv = N >> 2;
    for (int v = tid; v < nv; v += 256) {
        float4 s4 = rv[v];
        char4  c4 = cv[v];
        sr4[v] = s4;
        sc4[v] = c4;
        const int j0 = v << 2;

        float e;
        e = __expf(s4.x - 10.f);
        negsum += (c4.x != 3 && c4.x != lab) ? e : 0.f;
        pcnt   += (c4.x == lab && (j0 + 0) != i);
        e = __expf(s4.y - 10.f);
        negsum += (c4.y != 3 && c4.y != lab) ? e : 0.f;
        pcnt   += (c4.y == lab && (j0 + 1) != i);
        e = __expf(s4.z - 10.f);
        negsum += (c4.z != 3 && c4.z != lab) ? e : 0.f;
        pcnt   += (c4.z == lab && (j0 + 2) != i);
        e = __expf(s4.w - 10.f);
        negsum += (c4.w != 3 && c4.w != lab) ? e : 0.f;
        pcnt   += (c4.w == lab && (j0 + 3) != i);
    }

    negsum = wred_f(negsum);
    pcnt   = wred_i(pcnt);
    if ((tid & 31) == 0) { redf[tid >> 5] = negsum; redi[tid >> 5] = pcnt; }
    __syncthreads();
    if (tid == 0) {
        float t = 0.f; int p = 0;
#pragma unroll
        for (int w = 0; w < 8; w++) { t += redf[w]; p += redi[w]; }
        sL = (t > 0.f) ? (__logf(t) + 10.f) : -1e30f;
        sP = p;
    }
    __syncthreads();
    const float L = sL;
    const int   P = sP;

    if (L <= -1e29f) {                   // no negatives: not processed
        if (tid == 0) { g_rowloss[i] = 0.f; g_rowflag[i] = 0; }
        return;
    }
    if (P == 0) {                        // no positives: pos logit = 1/T = 10
        if (tid == 0) {
            float d = L - 10.f;
            float loss = (d > 0.f) ? d + log1pf(__expf(-d)) : log1pf(__expf(d));
            g_rowloss[i] = loss;
            g_rowflag[i] = 0;
        }
        return;
    }

    // pass 2: sum over positives of log(1 + exp(L - s))  (d in [-20, ~30], safe)
    float psum = 0.f;
    for (int v = tid; v < nv; v += 256) {
        float4 s4 = sr4[v];
        char4  c4 = sc4[v];
        const int j0 = v << 2;
        float t;
        t = log1pf(__expf(L - s4.x));
        psum += (c4.x == lab && (j0 + 0) != i) ? t : 0.f;
        t = log1pf(__expf(L - s4.y));
        psum += (c4.y == lab && (j0 + 1) != i) ? t : 0.f;
        t = log1pf(__expf(L - s4.z));
        psum += (c4.z == lab && (j0 + 2) != i) ? t : 0.f;
        t = log1pf(__expf(L - s4.w));
        psum += (c4.w == lab && (j0 + 3) != i) ? t : 0.f;
    }
    psum = wred_f(psum);
    if ((tid & 31) == 0) redf[tid >> 5] = psum;
    __syncthreads();
    if (tid == 0) {
        float t = 0.f;
#pragma unroll
        for (int w = 0; w < 8; w++) t += redf[w];
        g_rowloss[i] = t / (float)P;
        g_rowflag[i] = 1;
    }
}

// ---------------- kernel 4: final deterministic reduction -------------------
__global__ void __launch_bounds__(256) k_finalize(float* __restrict__ out, int N)
{
    const int tid = threadIdx.x;
    float s = 0.f;
    int c = 0;
    for (int j = tid; j < N; j += 256) {
        s += g_rowloss[j];
        c += g_rowflag[j];
    }
    s = wred_f(s);
    c = wred_i(c);
    __shared__ float redf[8];
    __shared__ int   redi[8];
    if ((tid & 31) == 0) { redf[tid >> 5] = s; redi[tid >> 5] = c; }
    __syncthreads();
    if (tid == 0) {
        float t = 0.f; int p = 0;
#pragma unroll
        for (int w = 0; w < 8; w++) { t += redf[w]; p += redi[w]; }
        out[0] = t / (float)(1 + p);
    }
}

// ---------------- launcher ---------------------------------------------------
extern "C" void kernel_launch(void* const* d_in, const int* in_sizes, int n_in,
                              void* d_out, int out_size)
{
    const float* feats  = (const float*)d_in[0];
    const int*   labels = (const int*)d_in[1];
    const int*   bad    = (const int*)d_in[2];
    float* out = (float*)d_out;

    const int N = in_sizes[1];            // 8192
    const int D = in_sizes[0] / N;        // 512

    k_normalize<<<N, 128>>>(feats, labels, bad, N, D);

    dim3 grid(N / 128, N / 128);
    k_gemm_tf32<<<grid, 256>>>(N, D);

    k_rowloss<<<N, 256>>>(N);
    k_finalize<<<1, 256>>>(out, N);
}

// round 3
// speedup vs baseline: 5.9001x; 1.5693x over previous
#include <cuda_runtime.h>
#include <cuda_fp16.h>
#include <math.h>
#include <stdint.h>

// Shapes fixed by the problem: N=8192, D=512, 3 classes
#define NMAX 8192
#define DMAX 512

// ---------------- device scratch (static, no runtime allocation) ------------
__device__ float  g_fn[(size_t)NMAX * DMAX];   // normalized, tf32-rounded (16 MB)
__device__ __half g_S[(size_t)NMAX * NMAX];    // scaled logits, fp16 (128 MB)
__device__ signed char g_code[NMAX];           // valid ? label(0..2) : 3
__device__ float g_rowloss[NMAX];
__device__ int   g_rowflag[NMAX];

// ---------------- helpers ----------------------------------------------------
__device__ __forceinline__ float tf32r(float x) {
    uint32_t u;
    asm("cvt.rna.tf32.f32 %0, %1;" : "=r"(u) : "f"(x));
    return __uint_as_float(u);
}

__device__ __forceinline__ float wred_f(float x) {
#pragma unroll
    for (int o = 16; o; o >>= 1) x += __shfl_xor_sync(0xffffffffu, x, o);
    return x;
}
__device__ __forceinline__ int wred_i(int x) {
#pragma unroll
    for (int o = 16; o; o >>= 1) x += __shfl_xor_sync(0xffffffffu, x, o);
    return x;
}

__device__ __forceinline__ void mma_tf32(float* d, const uint32_t* a, const uint32_t* b) {
    asm volatile(
        "mma.sync.aligned.m16n8k8.row.col.f32.tf32.tf32.f32 "
        "{%0,%1,%2,%3}, {%4,%5,%6,%7}, {%8,%9}, {%0,%1,%2,%3};"
        : "+f"(d[0]), "+f"(d[1]), "+f"(d[2]), "+f"(d[3])
        : "r"(a[0]), "r"(a[1]), "r"(a[2]), "r"(a[3]),
          "r"(b[0]), "r"(b[1]));
}

// ---------------- kernel 1: normalize + tf32-round + build code -------------
__global__ void __launch_bounds__(128) k_normalize(
    const float* __restrict__ feats,
    const int* __restrict__ labels,
    const int* __restrict__ bad,
    int N, int D)
{
    const int i = blockIdx.x;
    const int tid = threadIdx.x;
    float4 v = reinterpret_cast<const float4*>(feats + (size_t)i * D)[tid];
    float ss = v.x * v.x + v.y * v.y + v.z * v.z + v.w * v.w;
    ss = wred_f(ss);
    __shared__ float w[4];
    if ((tid & 31) == 0) w[tid >> 5] = ss;
    __syncthreads();
    float rinv = rsqrtf(w[0] + w[1] + w[2] + w[3]);
    float4 o4 = make_float4(tf32r(v.x * rinv), tf32r(v.y * rinv),
                            tf32r(v.z * rinv), tf32r(v.w * rinv));
    reinterpret_cast<float4*>(g_fn + (size_t)i * D)[tid] = o4;
    if (tid == 0) {
        g_code[i] = (bad[i] == 0) ? (signed char)labels[i] : (signed char)3;
    }
}

// ---------------- kernel 2: symmetric tf32 GEMM  S = (fn fn^T) * 10 ---------
// Only upper-triangle 128x128 tiles (2080 of 4096). Off-diagonal tiles also
// emit the mirrored tile via a smem transpose stage (reusing fragment smem).
#define NTILE 64  // N / 128

__global__ void __launch_bounds__(256) k_gemm_tf32(int N, int D)
{
    __shared__ __align__(16) unsigned char smem_raw[34816];
    float*  Asm = reinterpret_cast<float*>(smem_raw);            // 16 KB
    float*  Bsm = reinterpret_cast<float*>(smem_raw + 16384);    // 16 KB
    __half* Tsm = reinterpret_cast<__half*>(smem_raw);           // 33792 B (reused)

    // map linear block id -> upper-triangle (by, bx), bx >= by
    int t = blockIdx.x;
    int by = 0;
    {
        int rem = t;
        while (rem >= NTILE - by) { rem -= NTILE - by; by++; }
        t = rem;
    }
    const int bx = by + t;
    const int row0 = by * 128;
    const int col0 = bx * 128;

    const int tid  = threadIdx.x;
    const int lane = tid & 31;
    const int warp = tid >> 5;
    const int wm   = warp >> 2;       // 0..1
    const int wn   = warp & 3;        // 0..3

    const int lr = tid >> 3;          // 0..31
    const int lc = (tid & 7) << 2;    // 0..28

    const float* __restrict__ fn = g_fn;

    float acc[4][4][4];
#pragma unroll
    for (int a = 0; a < 4; a++)
#pragma unroll
        for (int b = 0; b < 4; b++)
#pragma unroll
            for (int c = 0; c < 4; c++) acc[a][b][c] = 0.f;

    float4 a4[4], b4[4];
#pragma unroll
    for (int r = 0; r < 4; r++) {
        a4[r] = *reinterpret_cast<const float4*>(fn + (size_t)(row0 + lr + 32 * r) * D + lc);
        b4[r] = *reinterpret_cast<const float4*>(fn + (size_t)(col0 + lr + 32 * r) * D + lc);
    }

    for (int k0 = 0; k0 < D; k0 += 32) {
        __syncthreads();

        // scatter current tile into fragment-permuted smem
#pragma unroll
        for (int r = 0; r < 4; r++) {
            const float av[4] = {a4[r].x, a4[r].y, a4[r].z, a4[r].w};
            const float bv[4] = {b4[r].x, b4[r].y, b4[r].z, b4[r].w};
            const int m  = lr + 32 * r;
            const int mt = m >> 4, rr = m & 15;
            const int nt = m >> 3, cc = m & 7;
#pragma unroll
            for (int c = 0; c < 4; c++) {
                const int kc = lc + c;
                const int ks = kc >> 3, k7 = kc & 7;
                const int swz = 5 * ks;
                const int laneA = ((((rr & 7) << 2) | (k7 & 3)) ^ swz);
                const int regA  = (rr >> 3) | ((k7 >> 2) << 1);
                Asm[(((ks << 3) + mt) << 7) + (laneA << 2) + regA] = av[c];
                const int laneB = (((cc << 2) | (k7 & 3)) ^ swz);
                const int regB  = k7 >> 2;
                Bsm[(((ks << 4) + nt) << 6) + (laneB << 1) + regB] = bv[c];
            }
        }
        __syncthreads();

        if (k0 + 32 < D) {
#pragma unroll
            for (int r = 0; r < 4; r++) {
                a4[r] = *reinterpret_cast<const float4*>(fn + (size_t)(row0 + lr + 32 * r) * D + lc + k0 + 32);
                b4[r] = *reinterpret_cast<const float4*>(fn + (size_t)(col0 + lr + 32 * r) * D + lc + k0 + 32);
            }
        }

#pragma unroll
        for (int ks = 0; ks < 4; ks++) {
            const int lsw = lane ^ (5 * ks);
            uint32_t A[4][4];
#pragma unroll
            for (int mt_ = 0; mt_ < 4; mt_++) {
                const int mt = (wm << 2) + mt_;
                float4 v = *reinterpret_cast<const float4*>(&Asm[(((ks << 3) + mt) << 7) + (lsw << 2)]);
                A[mt_][0] = __float_as_uint(v.x);
                A[mt_][1] = __float_as_uint(v.y);
                A[mt_][2] = __float_as_uint(v.z);
                A[mt_][3] = __float_as_uint(v.w);
            }
            uint32_t B[4][2];
#pragma unroll
            for (int nt_ = 0; nt_ < 4; nt_++) {
                const int nt = (wn << 2) + nt_;
                float2 v = *reinterpret_cast<const float2*>(&Bsm[(((ks << 4) + nt) << 6) + (lsw << 1)]);
                B[nt_][0] = __float_as_uint(v.x);
                B[nt_][1] = __float_as_uint(v.y);
            }
#pragma unroll
            for (int mt_ = 0; mt_ < 4; mt_++)
#pragma unroll
                for (int nt_ = 0; nt_ < 4; nt_++)
                    mma_tf32(acc[mt_][nt_], A[mt_], B[nt_]);
        }
    }
    __syncthreads();   // all smem reads done (Tsm reuse below)

    const float invT = 10.f;
    const int g = lane >> 2;
    const int tq = lane & 3;
    __half* __restrict__ S = g_S;

    // direct store (by, bx) tile, fp16
#pragma unroll
    for (int mt_ = 0; mt_ < 4; mt_++) {
        const int row = row0 + (wm << 6) + (mt_ << 4) + g;
#pragma unroll
        for (int nt_ = 0; nt_ < 4; nt_++) {
            const int col = col0 + (wn << 5) + (nt_ << 3) + (tq << 1);
            __half2 lo = __floats2half2_rn(acc[mt_][nt_][0] * invT, acc[mt_][nt_][1] * invT);
            __half2 hi = __floats2half2_rn(acc[mt_][nt_][2] * invT, acc[mt_][nt_][3] * invT);
            *reinterpret_cast<__half2*>(&S[(size_t)row * N + col]) = lo;
            *reinterpret_cast<__half2*>(&S[(size_t)(row + 8) * N + col]) = hi;
        }
    }

    // mirrored store (bx, by) tile via smem transpose (off-diagonal only)
    if (bx != by) {
        // stage: Tsm[c * 136 + r] = value(r, c)
#pragma unroll
        for (int mt_ = 0; mt_ < 4; mt_++) {
            const int r = (wm << 6) + (mt_ << 4) + g;
#pragma unroll
            for (int nt_ = 0; nt_ < 4; nt_++) {
                const int c = (wn << 5) + (nt_ << 3) + (tq << 1);
                Tsm[(c) * 136 + r]         = __float2half_rn(acc[mt_][nt_][0] * invT);
                Tsm[(c + 1) * 136 + r]     = __float2half_rn(acc[mt_][nt_][1] * invT);
                Tsm[(c) * 136 + r + 8]     = __float2half_rn(acc[mt_][nt_][2] * invT);
                Tsm[(c + 1) * 136 + r + 8] = __float2half_rn(acc[mt_][nt_][3] * invT);
            }
        }
        __syncthreads();
        // write out: transposed row tr (= original col), coalesced uint4
        const int tr  = tid >> 1;          // 0..127
        const int seg = (tid & 1) << 6;    // 0 or 64 halves
        const uint4* src = reinterpret_cast<const uint4*>(&Tsm[tr * 136 + seg]);
        uint4* dst = reinterpret_cast<uint4*>(&S[(size_t)(col0 + tr) * N + row0 + seg]);
#pragma unroll
        for (int k = 0; k < 8; k++) {
            dst[k] = src[k];
        }
    }
}

// ---------------- kernel 3: fused per-row loss (neg-lse + pos CE) ------------
__global__ void __launch_bounds__(256) k_rowloss(int N)
{
    __shared__ __half srow[NMAX];          // 16 KB row cache
    __shared__ uint32_t scw[NMAX / 4];     // 8 KB code cache (packed bytes)
    __shared__ float redf[8];
    __shared__ int   redi[8];
    __shared__ float sL;
    __shared__ int   sP;

    const int i = blockIdx.x;
    const int tid = threadIdx.x;

    const int ci = g_code[i];
    if (ci == 3) {
        if (tid == 0) { g_rowloss[i] = 0.f; g_rowflag[i] = 0; }
        return;
    }
    const int lab = ci;

    const uint4* __restrict__ rv  = reinterpret_cast<const uint4*>(g_S + (size_t)i * N);
    const uint2* __restrict__ cv8 = reinterpret_cast<const uint2*>(g_code);
    uint4* sr8 = reinterpret_cast<uint4*>(srow);
    uint2* sc8 = reinterpret_cast<uint2*>(scw);

    // pass 1: neg-sum of exp(s - 10), positive count; fill caches
    float negsum = 0.f;
    int   pcnt   = 0;
    const int nv = N >> 3;                 // 1024 groups of 8
    for (int v = tid; v < nv; v += 256) {
        uint4 w = rv[v];
        uint2 cw = cv8[v];
        sr8[v] = w;
        sc8[v] = cw;
        const int j0 = v << 3;

        float s[8];
        {
            float2 f;
            f = __half22float2(*reinterpret_cast<__half2*>(&w.x)); s[0] = f.x; s[1] = f.y;
            f = __half22float2(*reinterpret_cast<__half2*>(&w.y)); s[2] = f.x; s[3] = f.y;
            f = __half22float2(*reinterpret_cast<__half2*>(&w.z)); s[4] = f.x; s[5] = f.y;
            f = __half22float2(*reinterpret_cast<__half2*>(&w.w)); s[6] = f.x; s[7] = f.y;
        }
#pragma unroll
        for (int k = 0; k < 8; k++) {
            const int c = (int)((((k < 4) ? cw.x : cw.y) >> ((k & 3) * 8)) & 0xff);
            const float e = __expf(s[k] - 10.f);
            negsum += (c != 3 && c != lab) ? e : 0.f;
            pcnt   += (c == lab && (j0 + k) != i);
        }
    }

    negsum = wred_f(negsum);
    pcnt   = wred_i(pcnt);
    if ((tid & 31) == 0) { redf[tid >> 5] = negsum; redi[tid >> 5] = pcnt; }
    __syncthreads();
    if (tid == 0) {
        float tt = 0.f; int p = 0;
#pragma unroll
        for (int w = 0; w < 8; w++) { tt += redf[w]; p += redi[w]; }
        sL = (tt > 0.f) ? (__logf(tt) + 10.f) : -1e30f;
        sP = p;
    }
    __syncthreads();
    const float L = sL;
    const int   P = sP;

    if (L <= -1e29f) {
        if (tid == 0) { g_rowloss[i] = 0.f; g_rowflag[i] = 0; }
        return;
    }
    if (P == 0) {
        if (tid == 0) {
            float d = L - 10.f;
            float loss = (d > 0.f) ? d + log1pf(__expf(-d)) : log1pf(__expf(d));
            g_rowloss[i] = loss;
            g_rowflag[i] = 0;
        }
        return;
    }

    // pass 2: sum over positives of log1p(exp(L - s))
    float psum = 0.f;
    for (int v = tid; v < nv; v += 256) {
        uint4 w = sr8[v];
        uint2 cw = sc8[v];
        const int j0 = v << 3;
        float s[8];
        {
            float2 f;
            f = __half22float2(*reinterpret_cast<__half2*>(&w.x)); s[0] = f.x; s[1] = f.y;
            f = __half22float2(*reinterpret_cast<__half2*>(&w.y)); s[2] = f.x; s[3] = f.y;
            f = __half22float2(*reinterpret_cast<__half2*>(&w.z)); s[4] = f.x; s[5] = f.y;
            f = __half22float2(*reinterpret_cast<__half2*>(&w.w)); s[6] = f.x; s[7] = f.y;
        }
#pragma unroll
        for (int k = 0; k < 8; k++) {
            const int c = (int)((((k < 4) ? cw.x : cw.y) >> ((k & 3) * 8)) & 0xff);
            const float tv = log1pf(__expf(L - s[k]));
            psum += (c == lab && (j0 + k) != i) ? tv : 0.f;
        }
    }
    psum = wred_f(psum);
    if ((tid & 31) == 0) redf[tid >> 5] = psum;
    __syncthreads();
    if (tid == 0) {
        float tt = 0.f;
#pragma unroll
        for (int w = 0; w < 8; w++) tt += redf[w];
        g_rowloss[i] = tt / (float)P;
        g_rowflag[i] = 1;
    }
}

// ---------------- kernel 4: final deterministic reduction -------------------
__global__ void __launch_bounds__(256) k_finalize(float* __restrict__ out, int N)
{
    const int tid = threadIdx.x;
    float s = 0.f;
    int c = 0;
    for (int j = tid; j < N; j += 256) {
        s += g_rowloss[j];
        c += g_rowflag[j];
    }
    s = wred_f(s);
    c = wred_i(c);
    __shared__ float redf[8];
    __shared__ int   redi[8];
    if ((tid & 31) == 0) { redf[tid >> 5] = s; redi[tid >> 5] = c; }
    __syncthreads();
    if (tid == 0) {
        float tt = 0.f; int p = 0;
#pragma unroll
        for (int w = 0; w < 8; w++) { tt += redf[w]; p += redi[w]; }
        out[0] = tt / (float)(1 + p);
    }
}

// ---------------- launcher ---------------------------------------------------
extern "C" void kernel_launch(void* const* d_in, const int* in_sizes, int n_in,
                              void* d_out, int out_size)
{
    const float* feats  = (const float*)d_in[0];
    const int*   labels = (const int*)d_in[1];
    const int*   bad    = (const int*)d_in[2];
    float* out = (float*)d_out;

    const int N = in_sizes[1];            // 8192
    const int D = in_sizes[0] / N;        // 512

    k_normalize<<<N, 128>>>(feats, labels, bad, N, D);

    const int ntiles = (NTILE * (NTILE + 1)) / 2;   // 2080 upper-triangle tiles
    k_gemm_tf32<<<ntiles, 256>>>(N, D);

    k_rowloss<<<N, 256>>>(N);
    k_finalize<<<1, 256>>>(out, N);
}

// round 4
// speedup vs baseline: 8.4808x; 1.4374x over previous
#include <cuda_runtime.h>
#include <cuda_fp16.h>
#include <math.h>
#include <stdint.h>

// Shapes fixed by the problem: N=8192, D=512, 3 classes
#define NMAX 8192
#define DMAX 512

// ---------------- device scratch (static, no runtime allocation) ------------
__device__ __half g_fh[(size_t)NMAX * DMAX];   // normalized features, fp16 (8 MB)
__device__ __half g_S[(size_t)NMAX * NMAX];    // scaled logits, fp16 (128 MB)
__device__ signed char g_code[NMAX];           // valid ? label(0..2) : 3
__device__ float g_rowloss[NMAX];
__device__ int   g_rowflag[NMAX];

// ---------------- helpers ----------------------------------------------------
__device__ __forceinline__ float wred_f(float x) {
#pragma unroll
    for (int o = 16; o; o >>= 1) x += __shfl_xor_sync(0xffffffffu, x, o);
    return x;
}
__device__ __forceinline__ int wred_i(int x) {
#pragma unroll
    for (int o = 16; o; o >>= 1) x += __shfl_xor_sync(0xffffffffu, x, o);
    return x;
}

// fp16 tensor-core mma, fp32 accumulate
__device__ __forceinline__ void mma_f16(float* d, const uint32_t* a, const uint32_t* b) {
    asm volatile(
        "mma.sync.aligned.m16n8k16.row.col.f32.f16.f16.f32 "
        "{%0,%1,%2,%3}, {%4,%5,%6,%7}, {%8,%9}, {%0,%1,%2,%3};"
        : "+f"(d[0]), "+f"(d[1]), "+f"(d[2]), "+f"(d[3])
        : "r"(a[0]), "r"(a[1]), "r"(a[2]), "r"(a[3]),
          "r"(b[0]), "r"(b[1]));
}

// ---------------- kernel 1: normalize -> fp16 + build code ------------------
__global__ void __launch_bounds__(128) k_normalize(
    const float* __restrict__ feats,
    const int* __restrict__ labels,
    const int* __restrict__ bad,
    int N, int D)
{
    const int i = blockIdx.x;
    const int tid = threadIdx.x;
    float4 v = reinterpret_cast<const float4*>(feats + (size_t)i * D)[tid];
    float ss = v.x * v.x + v.y * v.y + v.z * v.z + v.w * v.w;
    ss = wred_f(ss);
    __shared__ float w[4];
    if ((tid & 31) == 0) w[tid >> 5] = ss;
    __syncthreads();
    float rinv = rsqrtf(w[0] + w[1] + w[2] + w[3]);
    uint2 o;
    __half2 h0 = __floats2half2_rn(v.x * rinv, v.y * rinv);
    __half2 h1 = __floats2half2_rn(v.z * rinv, v.w * rinv);
    o.x = *reinterpret_cast<uint32_t*>(&h0);
    o.y = *reinterpret_cast<uint32_t*>(&h1);
    reinterpret_cast<uint2*>(g_fh + (size_t)i * D)[tid] = o;
    if (tid == 0) {
        g_code[i] = (bad[i] == 0) ? (signed char)labels[i] : (signed char)3;
    }
}

// ---------------- kernel 2: symmetric fp16 GEMM  S = (fh fh^T) * 10 ---------
// Upper-triangle 128x128 tiles only (2080 of 4096); off-diagonal tiles also
// emit the mirrored tile via an smem transpose (reusing fragment smem).
// BK = 32 half2 units (64 k-halves) per iteration, 4 k-steps of m16n8k16.
// Smem holds fragment-permuted half2 slots (XOR-swizzled): compute side is
// pure LDS.128/LDS.64.
#define NTILE 64  // N / 128

__global__ void __launch_bounds__(256) k_gemm_f16(int N, int D)
{
    __shared__ __align__(16) unsigned char smem_raw[34816];
    uint32_t* Asm = reinterpret_cast<uint32_t*>(smem_raw);            // 16 KB
    uint32_t* Bsm = reinterpret_cast<uint32_t*>(smem_raw + 16384);    // 16 KB
    __half*   Tsm = reinterpret_cast<__half*>(smem_raw);              // reused

    // linear block id -> upper-triangle (by, bx), bx >= by
    int t = blockIdx.x;
    int by = 0;
    {
        int rem = t;
        while (rem >= NTILE - by) { rem -= NTILE - by; by++; }
        t = rem;
    }
    const int bx = by + t;
    const int row0 = by * 128;
    const int col0 = bx * 128;

    const int tid  = threadIdx.x;
    const int lane = tid & 31;
    const int warp = tid >> 5;
    const int wm   = warp >> 2;       // 0..1
    const int wn   = warp & 3;        // 0..3

    const int lr  = tid >> 3;         // 0..31 (row, x4 strided)
    const int lc2 = (tid & 7) << 2;   // 0..28 (half2-unit group of 4)

    const int D2 = D >> 1;            // row stride in half2 units (256)
    const uint32_t* __restrict__ fh2 = reinterpret_cast<const uint32_t*>(g_fh);

    float acc[4][4][4];
#pragma unroll
    for (int a = 0; a < 4; a++)
#pragma unroll
        for (int b = 0; b < 4; b++)
#pragma unroll
            for (int c = 0; c < 4; c++) acc[a][b][c] = 0.f;

    uint4 a4[4], b4[4];
#pragma unroll
    for (int r = 0; r < 4; r++) {
        a4[r] = *reinterpret_cast<const uint4*>(fh2 + (size_t)(row0 + lr + 32 * r) * D2 + lc2);
        b4[r] = *reinterpret_cast<const uint4*>(fh2 + (size_t)(col0 + lr + 32 * r) * D2 + lc2);
    }

    for (int k0 = 0; k0 < D2; k0 += 32) {     // 8 iterations
        __syncthreads();

        // scatter current tile into fragment-permuted smem (half2 slots)
#pragma unroll
        for (int r = 0; r < 4; r++) {
            const uint32_t av[4] = {a4[r].x, a4[r].y, a4[r].z, a4[r].w};
            const uint32_t bv[4] = {b4[r].x, b4[r].y, b4[r].z, b4[r].w};
            const int m  = lr + 32 * r;
            const int mt = m >> 4, rr = m & 15;
            const int nt = m >> 3, cc = m & 7;
#pragma unroll
            for (int c = 0; c < 4; c++) {
                const int kc = lc2 + c;           // half2 unit within BK (0..31)
                const int ks = kc >> 3, k7 = kc & 7;
                const int swz = 5 * ks;
                const int laneA = ((((rr & 7) << 2) | (k7 & 3)) ^ swz);
                const int regA  = (rr >> 3) | ((k7 >> 2) << 1);
                Asm[(((ks << 3) + mt) << 7) + (laneA << 2) + regA] = av[c];
                const int laneB = (((cc << 2) | (k7 & 3)) ^ swz);
                const int regB  = k7 >> 2;
                Bsm[(((ks << 4) + nt) << 6) + (laneB << 1) + regB] = bv[c];
            }
        }
        __syncthreads();

        // prefetch next tile
        if (k0 + 32 < D2) {
#pragma unroll
            for (int r = 0; r < 4; r++) {
                a4[r] = *reinterpret_cast<const uint4*>(fh2 + (size_t)(row0 + lr + 32 * r) * D2 + lc2 + k0 + 32);
                b4[r] = *reinterpret_cast<const uint4*>(fh2 + (size_t)(col0 + lr + 32 * r) * D2 + lc2 + k0 + 32);
            }
        }

        // 4 k-steps of m16n8k16
#pragma unroll
        for (int ks = 0; ks < 4; ks++) {
            const int lsw = lane ^ (5 * ks);
            uint32_t A[4][4];
#pragma unroll
            for (int mt_ = 0; mt_ < 4; mt_++) {
                const int mt = (wm << 2) + mt_;
                uint4 v = *reinterpret_cast<const uint4*>(&Asm[(((ks << 3) + mt) << 7) + (lsw << 2)]);
                A[mt_][0] = v.x; A[mt_][1] = v.y; A[mt_][2] = v.z; A[mt_][3] = v.w;
            }
            uint32_t B[4][2];
#pragma unroll
            for (int nt_ = 0; nt_ < 4; nt_++) {
                const int nt = (wn << 2) + nt_;
                uint2 v = *reinterpret_cast<const uint2*>(&Bsm[(((ks << 4) + nt) << 6) + (lsw << 1)]);
                B[nt_][0] = v.x; B[nt_][1] = v.y;
            }
#pragma unroll
            for (int mt_ = 0; mt_ < 4; mt_++)
#pragma unroll
                for (int nt_ = 0; nt_ < 4; nt_++)
                    mma_f16(acc[mt_][nt_], A[mt_], B[nt_]);
        }
    }
    __syncthreads();   // smem reads done (Tsm reuse below)

    const float invT = 10.f;
    const int g  = lane >> 2;
    const int tq = lane & 3;
    __half* __restrict__ S = g_S;

    // direct store (by, bx) tile
#pragma unroll
    for (int mt_ = 0; mt_ < 4; mt_++) {
        const int row = row0 + (wm << 6) + (mt_ << 4) + g;
#pragma unroll
        for (int nt_ = 0; nt_ < 4; nt_++) {
            const int col = col0 + (wn << 5) + (nt_ << 3) + (tq << 1);
            __half2 lo = __floats2half2_rn(acc[mt_][nt_][0] * invT, acc[mt_][nt_][1] * invT);
            __half2 hi = __floats2half2_rn(acc[mt_][nt_][2] * invT, acc[mt_][nt_][3] * invT);
            *reinterpret_cast<__half2*>(&S[(size_t)row * N + col]) = lo;
            *reinterpret_cast<__half2*>(&S[(size_t)(row + 8) * N + col]) = hi;
        }
    }

    // mirrored store (bx, by) via smem transpose (off-diagonal only)
    if (bx != by) {
#pragma unroll
        for (int mt_ = 0; mt_ < 4; mt_++) {
            const int r = (wm << 6) + (mt_ << 4) + g;
#pragma unroll
            for (int nt_ = 0; nt_ < 4; nt_++) {
                const int c = (wn << 5) + (nt_ << 3) + (tq << 1);
                Tsm[(c) * 136 + r]         = __float2half_rn(acc[mt_][nt_][0] * invT);
                Tsm[(c + 1) * 136 + r]     = __float2half_rn(acc[mt_][nt_][1] * invT);
                Tsm[(c) * 136 + r + 8]     = __float2half_rn(acc[mt_][nt_][2] * invT);
                Tsm[(c + 1) * 136 + r + 8] = __float2half_rn(acc[mt_][nt_][3] * invT);
            }
        }
        __syncthreads();
        const int tr  = tid >> 1;          // 0..127
        const int seg = (tid & 1) << 6;    // 0 or 64 halves
        const uint4* src = reinterpret_cast<const uint4*>(&Tsm[tr * 136 + seg]);
        uint4* dst = reinterpret_cast<uint4*>(&S[(size_t)(col0 + tr) * N + row0 + seg]);
#pragma unroll
        for (int k = 0; k < 8; k++) {
            dst[k] = src[k];
        }
    }
}

// ---------------- kernel 3: fused per-row loss (neg-lse + pos CE) ------------
__global__ void __launch_bounds__(256) k_rowloss(int N)
{
    __shared__ __half srow[NMAX];          // 16 KB row cache
    __shared__ uint32_t scw[NMAX / 4];     // 8 KB code cache
    __shared__ float redf[8];
    __shared__ int   redi[8];
    __shared__ float sL;
    __shared__ int   sP;

    const int i = blockIdx.x;
    const int tid = threadIdx.x;

    const int ci = g_code[i];
    if (ci == 3) {
        if (tid == 0) { g_rowloss[i] = 0.f; g_rowflag[i] = 0; }
        return;
    }
    const int lab = ci;

    const uint4* __restrict__ rv  = reinterpret_cast<const uint4*>(g_S + (size_t)i * N);
    const uint2* __restrict__ cv8 = reinterpret_cast<const uint2*>(g_code);
    uint4* sr8 = reinterpret_cast<uint4*>(srow);
    uint2* sc8 = reinterpret_cast<uint2*>(scw);

    // pass 1: neg-sum of exp(s - 10), positive count; fill caches
    float negsum = 0.f;
    int   pcnt   = 0;
    const int nv = N >> 3;
    for (int v = tid; v < nv; v += 256) {
        uint4 w = rv[v];
        uint2 cw = cv8[v];
        sr8[v] = w;
        sc8[v] = cw;
        const int j0 = v << 3;

        float s[8];
        {
            float2 f;
            f = __half22float2(*reinterpret_cast<__half2*>(&w.x)); s[0] = f.x; s[1] = f.y;
            f = __half22float2(*reinterpret_cast<__half2*>(&w.y)); s[2] = f.x; s[3] = f.y;
            f = __half22float2(*reinterpret_cast<__half2*>(&w.z)); s[4] = f.x; s[5] = f.y;
            f = __half22float2(*reinterpret_cast<__half2*>(&w.w)); s[6] = f.x; s[7] = f.y;
        }
#pragma unroll
        for (int k = 0; k < 8; k++) {
            const int c = (int)((((k < 4) ? cw.x : cw.y) >> ((k & 3) * 8)) & 0xff);
            const float e = __expf(s[k] - 10.f);
            negsum += (c != 3 && c != lab) ? e : 0.f;
            pcnt   += (c == lab && (j0 + k) != i);
        }
    }

    negsum = wred_f(negsum);
    pcnt   = wred_i(pcnt);
    if ((tid & 31) == 0) { redf[tid >> 5] = negsum; redi[tid >> 5] = pcnt; }
    __syncthreads();
    if (tid == 0) {
        float tt = 0.f; int p = 0;
#pragma unroll
        for (int w = 0; w < 8; w++) { tt += redf[w]; p += redi[w]; }
        sL = (tt > 0.f) ? (__logf(tt) + 10.f) : -1e30f;
        sP = p;
    }
    __syncthreads();
    const float L = sL;
    const int   P = sP;

    if (L <= -1e29f) {
        if (tid == 0) { g_rowloss[i] = 0.f; g_rowflag[i] = 0; }
        return;
    }
    if (P == 0) {
        if (tid == 0) {
            float d = L - 10.f;
            float loss = (d > 0.f) ? d + log1pf(__expf(-d)) : log1pf(__expf(d));
            g_rowloss[i] = loss;
            g_rowflag[i] = 0;
        }
        return;
    }

    // pass 2: sum over positives of log1p(exp(L - s))
    float psum = 0.f;
    for (int v = tid; v < nv; v += 256) {
        uint4 w = sr8[v];
        uint2 cw = sc8[v];
        const int j0 = v << 3;
        float s[8];
        {
            float2 f;
            f = __half22float2(*reinterpret_cast<__half2*>(&w.x)); s[0] = f.x; s[1] = f.y;
            f = __half22float2(*reinterpret_cast<__half2*>(&w.y)); s[2] = f.x; s[3] = f.y;
            f = __half22float2(*reinterpret_cast<__half2*>(&w.z)); s[4] = f.x; s[5] = f.y;
            f = __half22float2(*reinterpret_cast<__half2*>(&w.w)); s[6] = f.x; s[7] = f.y;
        }
#pragma unroll
        for (int k = 0; k < 8; k++) {
            const int c = (int)((((k < 4) ? cw.x : cw.y) >> ((k & 3) * 8)) & 0xff);
            const float tv = log1pf(__expf(L - s[k]));
            psum += (c == lab && (j0 + k) != i) ? tv : 0.f;
        }
    }
    psum = wred_f(psum);
    if ((tid & 31) == 0) redf[tid >> 5] = psum;
    __syncthreads();
    if (tid == 0) {
        float tt = 0.f;
#pragma unroll
        for (int w = 0; w < 8; w++) tt += redf[w];
        g_rowloss[i] = tt / (float)P;
        g_rowflag[i] = 1;
    }
}

// ---------------- kernel 4: final deterministic reduction -------------------
__global__ void __launch_bounds__(256) k_finalize(float* __restrict__ out, int N)
{
    const int tid = threadIdx.x;
    float s = 0.f;
    int c = 0;
    for (int j = tid; j < N; j += 256) {
        s += g_rowloss[j];
        c += g_rowflag[j];
    }
    s = wred_f(s);
    c = wred_i(c);
    __shared__ float redf[8];
    __shared__ int   redi[8];
    if ((tid & 31) == 0) { redf[tid >> 5] = s; redi[tid >> 5] = c; }
    __syncthreads();
    if (tid == 0) {
        float tt = 0.f; int p = 0;
#pragma unroll
        for (int w = 0; w < 8; w++) { tt += redf[w]; p += redi[w]; }
        out[0] = tt / (float)(1 + p);
    }
}

// ---------------- launcher ---------------------------------------------------
extern "C" void kernel_launch(void* const* d_in, const int* in_sizes, int n_in,
                              void* d_out, int out_size)
{
    const float* feats  = (const float*)d_in[0];
    const int*   labels = (const int*)d_in[1];
    const int*   bad    = (const int*)d_in[2];
    float* out = (float*)d_out;

    const int N = in_sizes[1];            // 8192
    const int D = in_sizes[0] / N;        // 512

    k_normalize<<<N, 128>>>(feats, labels, bad, N, D);

    const int ntiles = (NTILE * (NTILE + 1)) / 2;   // 2080 upper-triangle tiles
    k_gemm_f16<<<ntiles, 256>>>(N, D);

    k_rowloss<<<N, 256>>>(N);
    k_finalize<<<1, 256>>>(out, N);
}

// round 5
// speedup vs baseline: 21.2222x; 2.5024x over previous
#include <cuda_runtime.h>
#include <cuda_fp16.h>
#include <math.h>
#include <stdint.h>

// Shapes fixed by the problem: N=8192, D=512, 3 classes
#define NMAX 8192
#define DMAX 512

// ---------------- device scratch (static, no runtime allocation) ------------
__device__ __half g_fh[(size_t)NMAX * DMAX];   // permuted normalized features (8 MB)
__device__ __half g_S[(size_t)NMAX * NMAX];    // scaled logits, fp16 (valid block only)
__device__ int    g_perm[NMAX];                // sorted order: class0,1,2 valid, then invalid
__device__ int    g_bnd[4];                    // {0, b1, b2, NV} class boundaries
__device__ float  g_rowloss[NMAX];
__device__ int    g_rowflag[NMAX];

// ---------------- helpers ----------------------------------------------------
__device__ __forceinline__ float wred_f(float x) {
#pragma unroll
    for (int o = 16; o; o >>= 1) x += __shfl_xor_sync(0xffffffffu, x, o);
    return x;
}
__device__ __forceinline__ int wred_i(int x) {
#pragma unroll
    for (int o = 16; o; o >>= 1) x += __shfl_xor_sync(0xffffffffu, x, o);
    return x;
}

__device__ __forceinline__ void mma_f16(float* d, const uint32_t* a, const uint32_t* b) {
    asm volatile(
        "mma.sync.aligned.m16n8k16.row.col.f32.f16.f16.f32 "
        "{%0,%1,%2,%3}, {%4,%5,%6,%7}, {%8,%9}, {%0,%1,%2,%3};"
        : "+f"(d[0]), "+f"(d[1]), "+f"(d[2]), "+f"(d[3])
        : "r"(a[0]), "r"(a[1]), "r"(a[2]), "r"(a[3]),
          "r"(b[0]), "r"(b[1]));
}

// ---------------- kernel 0: stable counting sort (1 block) ------------------
// Buckets: class 0,1,2 (valid) then invalid(3). Deterministic, stable.
__global__ void __launch_bounds__(1024) k_perm(
    const int* __restrict__ labels,
    const int* __restrict__ bad,
    int N)
{
    __shared__ int scan[1024];
    __shared__ int tot[4];
    const int t = threadIdx.x;
    const int E = N / 1024;            // 8 elements per thread, contiguous chunk

    int code[8];
    int cnt[4] = {0, 0, 0, 0};
#pragma unroll
    for (int e = 0; e < E; e++) {
        const int j = t * E + e;
        const int c = (bad[j] == 0) ? labels[j] : 3;
        code[e] = c;
        cnt[c]++;
    }

    int pre[4];
#pragma unroll
    for (int c = 0; c < 4; c++) {
        scan[t] = cnt[c];
        __syncthreads();
        int acc = cnt[c];
        for (int off = 1; off < 1024; off <<= 1) {
            int v = (t >= off) ? scan[t - off] : 0;
            __syncthreads();
            acc += v;
            scan[t] = acc;
            __syncthreads();
        }
        pre[c] = acc - cnt[c];         // exclusive prefix
        if (t == 1023) tot[c] = acc;
        __syncthreads();
    }

    const int base0 = 0;
    const int base1 = tot[0];
    const int base2 = tot[0] + tot[1];
    const int base3 = tot[0] + tot[1] + tot[2];
    int base[4] = {base0, base1, base2, base3};

    int r[4] = {0, 0, 0, 0};
#pragma unroll
    for (int e = 0; e < E; e++) {
        const int j = t * E + e;
        const int c = code[e];
        g_perm[base[c] + pre[c] + r[c]] = j;
        r[c]++;
    }
    if (t == 0) {
        g_bnd[0] = 0;
        g_bnd[1] = base1;
        g_bnd[2] = base2;
        g_bnd[3] = base3;              // NV
    }
}

// ---------------- kernel 1: normalize + gather-permute -> fp16 --------------
__global__ void __launch_bounds__(128) k_normalize(
    const float* __restrict__ feats, int N, int D)
{
    const int i = blockIdx.x;            // destination (sorted) index
    const int tid = threadIdx.x;
    const int src = g_perm[i];
    float4 v = reinterpret_cast<const float4*>(feats + (size_t)src * D)[tid];
    float ss = v.x * v.x + v.y * v.y + v.z * v.z + v.w * v.w;
    ss = wred_f(ss);
    __shared__ float w[4];
    if ((tid & 31) == 0) w[tid >> 5] = ss;
    __syncthreads();
    float rinv = rsqrtf(w[0] + w[1] + w[2] + w[3]);
    uint2 o;
    __half2 h0 = __floats2half2_rn(v.x * rinv, v.y * rinv);
    __half2 h1 = __floats2half2_rn(v.z * rinv, v.w * rinv);
    o.x = *reinterpret_cast<uint32_t*>(&h0);
    o.y = *reinterpret_cast<uint32_t*>(&h1);
    reinterpret_cast<uint2*>(g_fh + (size_t)i * D)[tid] = o;
}

// ---------------- kernel 2: symmetric fp16 GEMM over valid block ------------
// Upper-triangle 128x128 tiles; blocks outside ceil(NV/128) exit immediately.
#define NTILE 64  // N / 128 (max)

__global__ void __launch_bounds__(256) k_gemm_f16(int N, int D)
{
    __shared__ __align__(16) unsigned char smem_raw[34816];
    uint32_t* Asm = reinterpret_cast<uint32_t*>(smem_raw);
    uint32_t* Bsm = reinterpret_cast<uint32_t*>(smem_raw + 16384);
    __half*   Tsm = reinterpret_cast<__half*>(smem_raw);

    // linear block id -> upper-triangle (by, bx), bx >= by  (over full 64 grid)
    int t = blockIdx.x;
    int by = 0;
    {
        int rem = t;
        while (rem >= NTILE - by) { rem -= NTILE - by; by++; }
        t = rem;
    }
    const int bx = by + t;

    const int NV  = g_bnd[3];
    const int ntv = (NV + 127) >> 7;
    if (bx >= ntv) return;               // by <= bx, so this covers both

    const int row0 = by * 128;
    const int col0 = bx * 128;

    const int tid  = threadIdx.x;
    const int lane = tid & 31;
    const int warp = tid >> 5;
    const int wm   = warp >> 2;
    const int wn   = warp & 3;

    const int lr  = tid >> 3;
    const int lc2 = (tid & 7) << 2;

    const int D2 = D >> 1;
    const uint32_t* __restrict__ fh2 = reinterpret_cast<const uint32_t*>(g_fh);

    float acc[4][4][4];
#pragma unroll
    for (int a = 0; a < 4; a++)
#pragma unroll
        for (int b = 0; b < 4; b++)
#pragma unroll
            for (int c = 0; c < 4; c++) acc[a][b][c] = 0.f;

    uint4 a4[4], b4[4];
#pragma unroll
    for (int r = 0; r < 4; r++) {
        a4[r] = *reinterpret_cast<const uint4*>(fh2 + (size_t)(row0 + lr + 32 * r) * D2 + lc2);
        b4[r] = *reinterpret_cast<const uint4*>(fh2 + (size_t)(col0 + lr + 32 * r) * D2 + lc2);
    }

    for (int k0 = 0; k0 < D2; k0 += 32) {
        __syncthreads();
#pragma unroll
        for (int r = 0; r < 4; r++) {
            const uint32_t av[4] = {a4[r].x, a4[r].y, a4[r].z, a4[r].w};
            const uint32_t bv[4] = {b4[r].x, b4[r].y, b4[r].z, b4[r].w};
            const int m  = lr + 32 * r;
            const int mt = m >> 4, rr = m & 15;
            const int nt = m >> 3, cc = m & 7;
#pragma unroll
            for (int c = 0; c < 4; c++) {
                const int kc = lc2 + c;
                const int ks = kc >> 3, k7 = kc & 7;
                const int swz = 5 * ks;
                const int laneA = ((((rr & 7) << 2) | (k7 & 3)) ^ swz);
                const int regA  = (rr >> 3) | ((k7 >> 2) << 1);
                Asm[(((ks << 3) + mt) << 7) + (laneA << 2) + regA] = av[c];
                const int laneB = (((cc << 2) | (k7 & 3)) ^ swz);
                const int regB  = k7 >> 2;
                Bsm[(((ks << 4) + nt) << 6) + (laneB << 1) + regB] = bv[c];
            }
        }
        __syncthreads();

        if (k0 + 32 < D2) {
#pragma unroll
            for (int r = 0; r < 4; r++) {
                a4[r] = *reinterpret_cast<const uint4*>(fh2 + (size_t)(row0 + lr + 32 * r) * D2 + lc2 + k0 + 32);
                b4[r] = *reinterpret_cast<const uint4*>(fh2 + (size_t)(col0 + lr + 32 * r) * D2 + lc2 + k0 + 32);
            }
        }

#pragma unroll
        for (int ks = 0; ks < 4; ks++) {
            const int lsw = lane ^ (5 * ks);
            uint32_t A[4][4];
#pragma unroll
            for (int mt_ = 0; mt_ < 4; mt_++) {
                const int mt = (wm << 2) + mt_;
                uint4 v = *reinterpret_cast<const uint4*>(&Asm[(((ks << 3) + mt) << 7) + (lsw << 2)]);
                A[mt_][0] = v.x; A[mt_][1] = v.y; A[mt_][2] = v.z; A[mt_][3] = v.w;
            }
            uint32_t B[4][2];
#pragma unroll
            for (int nt_ = 0; nt_ < 4; nt_++) {
                const int nt = (wn << 2) + nt_;
                uint2 v = *reinterpret_cast<const uint2*>(&Bsm[(((ks << 4) + nt) << 6) + (lsw << 1)]);
                B[nt_][0] = v.x; B[nt_][1] = v.y;
            }
#pragma unroll
            for (int mt_ = 0; mt_ < 4; mt_++)
#pragma unroll
                for (int nt_ = 0; nt_ < 4; nt_++)
                    mma_f16(acc[mt_][nt_], A[mt_], B[nt_]);
        }
    }
    __syncthreads();

    const float invT = 10.f;
    const int g  = lane >> 2;
    const int tq = lane & 3;
    __half* __restrict__ S = g_S;

#pragma unroll
    for (int mt_ = 0; mt_ < 4; mt_++) {
        const int row = row0 + (wm << 6) + (mt_ << 4) + g;
#pragma unroll
        for (int nt_ = 0; nt_ < 4; nt_++) {
            const int col = col0 + (wn << 5) + (nt_ << 3) + (tq << 1);
            __half2 lo = __floats2half2_rn(acc[mt_][nt_][0] * invT, acc[mt_][nt_][1] * invT);
            __half2 hi = __floats2half2_rn(acc[mt_][nt_][2] * invT, acc[mt_][nt_][3] * invT);
            *reinterpret_cast<__half2*>(&S[(size_t)row * N + col]) = lo;
            *reinterpret_cast<__half2*>(&S[(size_t)(row + 8) * N + col]) = hi;
        }
    }

    if (bx != by) {
#pragma unroll
        for (int mt_ = 0; mt_ < 4; mt_++) {
            const int r = (wm << 6) + (mt_ << 4) + g;
#pragma unroll
            for (int nt_ = 0; nt_ < 4; nt_++) {
                const int c = (wn << 5) + (nt_ << 3) + (tq << 1);
                Tsm[(c) * 136 + r]         = __float2half_rn(acc[mt_][nt_][0] * invT);
                Tsm[(c + 1) * 136 + r]     = __float2half_rn(acc[mt_][nt_][1] * invT);
                Tsm[(c) * 136 + r + 8]     = __float2half_rn(acc[mt_][nt_][2] * invT);
                Tsm[(c + 1) * 136 + r + 8] = __float2half_rn(acc[mt_][nt_][3] * invT);
            }
        }
        __syncthreads();
        const int tr  = tid >> 1;
        const int seg = (tid & 1) << 6;
        const uint4* src = reinterpret_cast<const uint4*>(&Tsm[tr * 136 + seg]);
        uint4* dst = reinterpret_cast<uint4*>(&S[(size_t)(col0 + tr) * N + row0 + seg]);
#pragma unroll
        for (int k = 0; k < 8; k++) dst[k] = src[k];
    }
}

// ---------------- kernel 3: per-row loss over sorted ranges -----------------
// Row i (< NV): positives = [lo, hi) \ {i} (its class range), negatives =
// [0, lo) u [hi, NV). No predicates, exp only where needed.
__global__ void __launch_bounds__(256) k_rowloss(int N)
{
    __shared__ float redf[8];
    __shared__ float sL;

    const int i = blockIdx.x;
    const int tid = threadIdx.x;

    const int b1 = g_bnd[1];
    const int b2 = g_bnd[2];
    const int NV = g_bnd[3];

    if (i >= NV) {
        if (tid == 0) { g_rowloss[i] = 0.f; g_rowflag[i] = 0; }
        return;
    }

    const int lo = (i < b1) ? 0  : ((i < b2) ? b1 : b2);
    const int hi = (i < b1) ? b1 : ((i < b2) ? b2 : NV);
    const int P  = hi - lo - 1;

    const __half* __restrict__ row = g_S + (size_t)i * N;

    // pass 1: negsum = sum exp(s - 10) over [0, lo) u [hi, NV)
    float negsum = 0.f;
    for (int j = tid; j < lo; j += 256)
        negsum += __expf(__half2float(row[j]) - 10.f);
    for (int j = hi + tid; j < NV; j += 256)
        negsum += __expf(__half2float(row[j]) - 10.f);

    negsum = wred_f(negsum);
    if ((tid & 31) == 0) redf[tid >> 5] = negsum;
    __syncthreads();
    if (tid == 0) {
        float tt = 0.f;
#pragma unroll
        for (int w = 0; w < 8; w++) tt += redf[w];
        sL = (tt > 0.f) ? (__logf(tt) + 10.f) : -1e30f;
    }
    __syncthreads();
    const float L = sL;

    if (L <= -1e29f) {                  // no negatives: not processed
        if (tid == 0) { g_rowloss[i] = 0.f; g_rowflag[i] = 0; }
        return;
    }
    if (P == 0) {                       // no positives: pos logit = 1/T = 10
        if (tid == 0) {
            float d = L - 10.f;
            float loss = (d > 0.f) ? d + log1pf(__expf(-d)) : log1pf(__expf(d));
            g_rowloss[i] = loss;
            g_rowflag[i] = 0;
        }
        return;
    }

    // pass 2: psum = sum over positives of log1p(exp(L - s)), skip self
    float psum = 0.f;
    for (int j = lo + tid; j < hi; j += 256) {
        if (j == i) continue;
        psum += log1pf(__expf(L - __half2float(row[j])));
    }
    psum = wred_f(psum);
    if ((tid & 31) == 0) redf[tid >> 5] = psum;
    __syncthreads();
    if (tid == 0) {
        float tt = 0.f;
#pragma unroll
        for (int w = 0; w < 8; w++) tt += redf[w];
        g_rowloss[i] = tt / (float)P;
        g_rowflag[i] = 1;
    }
}

// ---------------- kernel 4: final deterministic reduction -------------------
__global__ void __launch_bounds__(256) k_finalize(float* __restrict__ out, int N)
{
    const int tid = threadIdx.x;
    float s = 0.f;
    int c = 0;
    for (int j = tid; j < N; j += 256) {
        s += g_rowloss[j];
        c += g_rowflag[j];
    }
    s = wred_f(s);
    c = wred_i(c);
    __shared__ float redf[8];
    __shared__ int   redi[8];
    if ((tid & 31) == 0) { redf[tid >> 5] = s; redi[tid >> 5] = c; }
    __syncthreads();
    if (tid == 0) {
        float tt = 0.f; int p = 0;
#pragma unroll
        for (int w = 0; w < 8; w++) { tt += redf[w]; p += redi[w]; }
        out[0] = tt / (float)(1 + p);
    }
}

// ---------------- launcher ---------------------------------------------------
extern "C" void kernel_launch(void* const* d_in, const int* in_sizes, int n_in,
                              void* d_out, int out_size)
{
    const float* feats  = (const float*)d_in[0];
    const int*   labels = (const int*)d_in[1];
    const int*   bad    = (const int*)d_in[2];
    float* out = (float*)d_out;

    const int N = in_sizes[1];            // 8192
    const int D = in_sizes[0] / N;        // 512

    k_perm<<<1, 1024>>>(labels, bad, N);
    k_normalize<<<N, 128>>>(feats, N, D);

    const int ntiles = (NTILE * (NTILE + 1)) / 2;   // 2080 (most exit early)
    k_gemm_f16<<<ntiles, 256>>>(N, D);

    k_rowloss<<<N, 256>>>(N);
    k_finalize<<<1, 256>>>(out, N);
}

// round 6
// speedup vs baseline: 23.3727x; 1.1013x over previous
#include <cuda_runtime.h>
#include <cuda_fp16.h>
#include <math.h>
#include <stdint.h>

// Shapes fixed by the problem: N=8192, D=512, 3 classes
#define NMAX 8192
#define DMAX 512

// ---------------- device scratch (static, no runtime allocation) ------------
__device__ __half g_fh[(size_t)NMAX * DMAX];   // permuted normalized features (8 MB)
__device__ __half g_S[(size_t)NMAX * NMAX];    // scaled logits, fp16 (class tiles only)
__device__ float  g_negpart[(size_t)NMAX * 64];// per-(row, col-tile) exp partials (2 MB)
__device__ int    g_perm[NMAX];                // sorted order: class0,1,2 valid, invalid
__device__ int    g_bnd[4];                    // {0, b1, b2, NV}
__device__ float  g_rowloss[NMAX];
__device__ int    g_rowflag[NMAX];

// ---------------- helpers ----------------------------------------------------
__device__ __forceinline__ float wred_f(float x) {
#pragma unroll
    for (int o = 16; o; o >>= 1) x += __shfl_xor_sync(0xffffffffu, x, o);
    return x;
}
__device__ __forceinline__ int wred_i(int x) {
#pragma unroll
    for (int o = 16; o; o >>= 1) x += __shfl_xor_sync(0xffffffffu, x, o);
    return x;
}

__device__ __forceinline__ void mma_f16(float* d, const uint32_t* a, const uint32_t* b) {
    asm volatile(
        "mma.sync.aligned.m16n8k16.row.col.f32.f16.f16.f32 "
        "{%0,%1,%2,%3}, {%4,%5,%6,%7}, {%8,%9}, {%0,%1,%2,%3};"
        : "+f"(d[0]), "+f"(d[1]), "+f"(d[2]), "+f"(d[3])
        : "r"(a[0]), "r"(a[1]), "r"(a[2]), "r"(a[3]),
          "r"(b[0]), "r"(b[1]));
}

// ---------------- kernel 0: stable counting sort (1 block, warp scans) ------
__global__ void __launch_bounds__(1024) k_perm(
    const int* __restrict__ labels,
    const int* __restrict__ bad,
    int N)
{
    __shared__ uint32_t wt01[32], wt23[32];
    const int t = threadIdx.x;
    const int lane = t & 31;
    const int wid = t >> 5;
    const int E = N / 1024;              // 8, contiguous chunk per thread

    int code[8];
    int cnt[4] = {0, 0, 0, 0};
#pragma unroll
    for (int e = 0; e < E; e++) {
        const int j = t * E + e;
        const int c = (bad[j] == 0) ? labels[j] : 3;
        code[e] = c;
        cnt[c]++;
    }

    // pack counts into 16-bit fields (totals <= 8192 fit)
    uint32_t v01 = (uint32_t)cnt[0] | ((uint32_t)cnt[1] << 16);
    uint32_t v23 = (uint32_t)cnt[2] | ((uint32_t)cnt[3] << 16);
    uint32_t s01 = v01, s23 = v23;
#pragma unroll
    for (int off = 1; off < 32; off <<= 1) {
        uint32_t t1 = __shfl_up_sync(0xffffffffu, s01, off);
        uint32_t t2 = __shfl_up_sync(0xffffffffu, s23, off);
        if (lane >= off) { s01 += t1; s23 += t2; }
    }
    if (lane == 31) { wt01[wid] = s01; wt23[wid] = s23; }
    __syncthreads();
    if (wid == 0) {
        uint32_t w1 = wt01[lane], w2 = wt23[lane];
#pragma unroll
        for (int off = 1; off < 32; off <<= 1) {
            uint32_t t1 = __shfl_up_sync(0xffffffffu, w1, off);
            uint32_t t2 = __shfl_up_sync(0xffffffffu, w2, off);
            if (lane >= off) { w1 += t1; w2 += t2; }
        }
        wt01[lane] = w1; wt23[lane] = w2;
    }
    __syncthreads();

    const uint32_t wp01 = wid ? wt01[wid - 1] : 0u;
    const uint32_t wp23 = wid ? wt23[wid - 1] : 0u;
    const uint32_t tt01 = wt01[31], tt23 = wt23[31];

    const uint32_t ep01 = wp01 + s01 - v01;   // exclusive thread prefix
    const uint32_t ep23 = wp23 + s23 - v23;
    int pre[4] = { (int)(ep01 & 0xffffu), (int)(ep01 >> 16),
                   (int)(ep23 & 0xffffu), (int)(ep23 >> 16) };
    const int tot0 = (int)(tt01 & 0xffffu);
    const int tot1 = (int)(tt01 >> 16);
    const int tot2 = (int)(tt23 & 0xffffu);
    int base[4] = { 0, tot0, tot0 + tot1, tot0 + tot1 + tot2 };

    int r[4] = {0, 0, 0, 0};
#pragma unroll
    for (int e = 0; e < E; e++) {
        const int j = t * E + e;
        const int c = code[e];
        g_perm[base[c] + pre[c] + r[c]] = j;
        r[c]++;
    }
    if (t == 0) {
        g_bnd[0] = 0;
        g_bnd[1] = base[1];
        g_bnd[2] = base[2];
        g_bnd[3] = base[3];              // NV
    }
}

// ---------------- kernel 1: normalize + gather-permute -> fp16 --------------
__global__ void __launch_bounds__(128) k_normalize(
    const float* __restrict__ feats, int N, int D)
{
    const int i = blockIdx.x;
    const int tid = threadIdx.x;
    const int src = g_perm[i];
    float4 v = reinterpret_cast<const float4*>(feats + (size_t)src * D)[tid];
    float ss = v.x * v.x + v.y * v.y + v.z * v.z + v.w * v.w;
    ss = wred_f(ss);
    __shared__ float w[4];
    if ((tid & 31) == 0) w[tid >> 5] = ss;
    __syncthreads();
    float rinv = rsqrtf(w[0] + w[1] + w[2] + w[3]);
    uint2 o;
    __half2 h0 = __floats2half2_rn(v.x * rinv, v.y * rinv);
    __half2 h1 = __floats2half2_rn(v.z * rinv, v.w * rinv);
    o.x = *reinterpret_cast<uint32_t*>(&h0);
    o.y = *reinterpret_cast<uint32_t*>(&h1);
    reinterpret_cast<uint2*>(g_fh + (size_t)i * D)[tid] = o;
}

// ---------------- kernel 2: symmetric fp16 GEMM + fused neg-exp partials ----
// Upper-triangle 128x128 tiles over the valid block. Epilogue computes the
// masked exp(s-10) row partials (and col partials for the mirror) and writes
// one deterministic slot per (row, col-tile). S is stored to global ONLY for
// tiles intersecting a same-class (positive) region.
#define NTILE 64  // N / 128 (max)

__global__ void __launch_bounds__(256) k_gemm_f16(int N, int D)
{
    __shared__ __align__(16) unsigned char smem_raw[34816];
    uint32_t* Asm = reinterpret_cast<uint32_t*>(smem_raw);
    uint32_t* Bsm = reinterpret_cast<uint32_t*>(smem_raw + 16384);
    __half*   Tsm = reinterpret_cast<__half*>(smem_raw);
    float*    SRow = reinterpret_cast<float*>(smem_raw);          // [128][4]
    float*    SCol = reinterpret_cast<float*>(smem_raw + 2048);   // [128][2]

    int t = blockIdx.x;
    int by = 0;
    {
        int rem = t;
        while (rem >= NTILE - by) { rem -= NTILE - by; by++; }
        t = rem;
    }
    const int bx = by + t;

    const int b1 = g_bnd[1];
    const int b2 = g_bnd[2];
    const int NV = g_bnd[3];
    const int ntv = (NV + 127) >> 7;
    if (bx >= ntv) return;

    const int row0 = by * 128;
    const int col0 = bx * 128;

    const int tid  = threadIdx.x;
    const int lane = tid & 31;
    const int warp = tid >> 5;
    const int wm   = warp >> 2;
    const int wn   = warp & 3;

    const int lr  = tid >> 3;
    const int lc2 = (tid & 7) << 2;

    const int D2 = D >> 1;
    const uint32_t* __restrict__ fh2 = reinterpret_cast<const uint32_t*>(g_fh);

    float acc[4][4][4];
#pragma unroll
    for (int a = 0; a < 4; a++)
#pragma unroll
        for (int b = 0; b < 4; b++)
#pragma unroll
            for (int c = 0; c < 4; c++) acc[a][b][c] = 0.f;

    uint4 a4[4], b4[4];
#pragma unroll
    for (int r = 0; r < 4; r++) {
        a4[r] = *reinterpret_cast<const uint4*>(fh2 + (size_t)(row0 + lr + 32 * r) * D2 + lc2);
        b4[r] = *reinterpret_cast<const uint4*>(fh2 + (size_t)(col0 + lr + 32 * r) * D2 + lc2);
    }

    for (int k0 = 0; k0 < D2; k0 += 32) {
        __syncthreads();
#pragma unroll
        for (int r = 0; r < 4; r++) {
            const uint32_t av[4] = {a4[r].x, a4[r].y, a4[r].z, a4[r].w};
            const uint32_t bv[4] = {b4[r].x, b4[r].y, b4[r].z, b4[r].w};
            const int m  = lr + 32 * r;
            const int mt = m >> 4, rr = m & 15;
            const int nt = m >> 3, cc = m & 7;
#pragma unroll
            for (int c = 0; c < 4; c++) {
                const int kc = lc2 + c;
                const int ks = kc >> 3, k7 = kc & 7;
                const int swz = 5 * ks;
                const int laneA = ((((rr & 7) << 2) | (k7 & 3)) ^ swz);
                const int regA  = (rr >> 3) | ((k7 >> 2) << 1);
                Asm[(((ks << 3) + mt) << 7) + (laneA << 2) + regA] = av[c];
                const int laneB = (((cc << 2) | (k7 & 3)) ^ swz);
                const int regB  = k7 >> 2;
                Bsm[(((ks << 4) + nt) << 6) + (laneB << 1) + regB] = bv[c];
            }
        }
        __syncthreads();

        if (k0 + 32 < D2) {
#pragma unroll
            for (int r = 0; r < 4; r++) {
                a4[r] = *reinterpret_cast<const uint4*>(fh2 + (size_t)(row0 + lr + 32 * r) * D2 + lc2 + k0 + 32);
                b4[r] = *reinterpret_cast<const uint4*>(fh2 + (size_t)(col0 + lr + 32 * r) * D2 + lc2 + k0 + 32);
            }
        }

#pragma unroll
        for (int ks = 0; ks < 4; ks++) {
            const int lsw = lane ^ (5 * ks);
            uint32_t A[4][4];
#pragma unroll
            for (int mt_ = 0; mt_ < 4; mt_++) {
                const int mt = (wm << 2) + mt_;
                uint4 v = *reinterpret_cast<const uint4*>(&Asm[(((ks << 3) + mt) << 7) + (lsw << 2)]);
                A[mt_][0] = v.x; A[mt_][1] = v.y; A[mt_][2] = v.z; A[mt_][3] = v.w;
            }
            uint32_t B[4][2];
#pragma unroll
            for (int nt_ = 0; nt_ < 4; nt_++) {
                const int nt = (wn << 2) + nt_;
                uint2 v = *reinterpret_cast<const uint2*>(&Bsm[(((ks << 4) + nt) << 6) + (lsw << 1)]);
                B[nt_][0] = v.x; B[nt_][1] = v.y;
            }
#pragma unroll
            for (int mt_ = 0; mt_ < 4; mt_++)
#pragma unroll
                for (int nt_ = 0; nt_ < 4; nt_++)
                    mma_f16(acc[mt_][nt_], A[mt_], B[nt_]);
        }
    }
    __syncthreads();   // mainloop smem dead; SRow/SCol/Tsm reuse below

    const float invT = 10.f;
    const int g  = lane >> 2;
    const int tq = lane & 3;

    // does this tile intersect any same-class (positive) block?
    bool storeT;
    {
        const int r0 = row0, r1 = row0 + 128, c0 = col0, c1 = col0 + 128;
        storeT = (r0 < b1 && r1 > 0  && c0 < b1 && c1 > 0)
              || (r0 < b2 && r1 > b1 && c0 < b2 && c1 > b1)
              || (r0 < NV && r1 > b2 && c0 < NV && c1 > b2);
    }

    // -- direct S store (only if class-intersecting) --
    if (storeT) {
        __half* __restrict__ S = g_S;
#pragma unroll
        for (int mt_ = 0; mt_ < 4; mt_++) {
            const int row = row0 + (wm << 6) + (mt_ << 4) + g;
#pragma unroll
            for (int nt_ = 0; nt_ < 4; nt_++) {
                const int col = col0 + (wn << 5) + (nt_ << 3) + (tq << 1);
                __half2 lo = __floats2half2_rn(acc[mt_][nt_][0] * invT, acc[mt_][nt_][1] * invT);
                __half2 hi = __floats2half2_rn(acc[mt_][nt_][2] * invT, acc[mt_][nt_][3] * invT);
                *reinterpret_cast<__half2*>(&S[(size_t)row * N + col]) = lo;
                *reinterpret_cast<__half2*>(&S[(size_t)(row + 8) * N + col]) = hi;
            }
        }
    }

    // -- masked exp partials: per-row (this tile) and per-col (mirror) --
    int rcls[8], ccls[8];
#pragma unroll
    for (int mt_ = 0; mt_ < 4; mt_++)
#pragma unroll
        for (int h = 0; h < 2; h++) {
            const int r = row0 + (wm << 6) + (mt_ << 4) + g + 8 * h;
            rcls[mt_ * 2 + h] = (r < b1) ? 0 : (r < b2) ? 1 : (r < NV) ? 2 : 3;
        }
#pragma unroll
    for (int nt_ = 0; nt_ < 4; nt_++)
#pragma unroll
        for (int c = 0; c < 2; c++) {
            const int cc = col0 + (wn << 5) + (nt_ << 3) + (tq << 1) + c;
            ccls[nt_ * 2 + c] = (cc < b1) ? 0 : (cc < b2) ? 1 : (cc < NV) ? 2 : 3;
        }

    float rsum[8] = {0, 0, 0, 0, 0, 0, 0, 0};
    float csum[8] = {0, 0, 0, 0, 0, 0, 0, 0};
#pragma unroll
    for (int mt_ = 0; mt_ < 4; mt_++)
#pragma unroll
        for (int h = 0; h < 2; h++) {
            const int rc = rcls[mt_ * 2 + h];
#pragma unroll
            for (int nt_ = 0; nt_ < 4; nt_++)
#pragma unroll
                for (int c = 0; c < 2; c++) {
                    const int cc = ccls[nt_ * 2 + c];
                    const float s = acc[mt_][nt_][2 * h + c] * invT;
                    const float e = __expf(s - 10.f);
                    const bool m = (rc != cc) && (rc != 3) && (cc != 3);
                    const float ev = m ? e : 0.f;
                    rsum[mt_ * 2 + h] += ev;
                    csum[nt_ * 2 + c] += ev;
                }
        }

    // reduce rows over tq (xor 1,2), cols over g (xor 4,8,16)
#pragma unroll
    for (int k = 0; k < 8; k++) {
        rsum[k] += __shfl_xor_sync(0xffffffffu, rsum[k], 1);
        rsum[k] += __shfl_xor_sync(0xffffffffu, rsum[k], 2);
        csum[k] += __shfl_xor_sync(0xffffffffu, csum[k], 4);
        csum[k] += __shfl_xor_sync(0xffffffffu, csum[k], 8);
        csum[k] += __shfl_xor_sync(0xffffffffu, csum[k], 16);
    }
    if (tq == 0) {
#pragma unroll
        for (int mt_ = 0; mt_ < 4; mt_++)
#pragma unroll
            for (int h = 0; h < 2; h++) {
                const int rl = (wm << 6) + (mt_ << 4) + g + 8 * h;
                SRow[rl * 4 + wn] = rsum[mt_ * 2 + h];
            }
    }
    if (g == 0) {
#pragma unroll
        for (int nt_ = 0; nt_ < 4; nt_++)
#pragma unroll
            for (int c = 0; c < 2; c++) {
                const int cl = (wn << 5) + (nt_ << 3) + (tq << 1) + c;
                SCol[cl * 2 + wm] = csum[nt_ * 2 + c];
            }
    }
    __syncthreads();

    if (tid < 128) {
        const float rp = SRow[tid * 4 + 0] + SRow[tid * 4 + 1]
                       + SRow[tid * 4 + 2] + SRow[tid * 4 + 3];
        g_negpart[(size_t)(row0 + tid) * 64 + bx] = rp;
    } else if (bx != by) {
        const int c = tid - 128;
        const float cp = SCol[c * 2 + 0] + SCol[c * 2 + 1];
        g_negpart[(size_t)(col0 + c) * 64 + by] = cp;
    }

    // -- mirror S store (class-intersecting, off-diagonal) --
    if (storeT && bx != by) {
        __syncthreads();    // partial LDS reads done; Tsm may overwrite
#pragma unroll
        for (int mt_ = 0; mt_ < 4; mt_++) {
            const int r = (wm << 6) + (mt_ << 4) + g;
#pragma unroll
            for (int nt_ = 0; nt_ < 4; nt_++) {
                const int c = (wn << 5) + (nt_ << 3) + (tq << 1);
                Tsm[(c) * 136 + r]         = __float2half_rn(acc[mt_][nt_][0] * invT);
                Tsm[(c + 1) * 136 + r]     = __float2half_rn(acc[mt_][nt_][1] * invT);
                Tsm[(c) * 136 + r + 8]     = __float2half_rn(acc[mt_][nt_][2] * invT);
                Tsm[(c + 1) * 136 + r + 8] = __float2half_rn(acc[mt_][nt_][3] * invT);
            }
        }
        __syncthreads();
        const int tr  = tid >> 1;
        const int seg = (tid & 1) << 6;
        const uint4* src = reinterpret_cast<const uint4*>(&Tsm[tr * 136 + seg]);
        uint4* dst = reinterpret_cast<uint4*>(&g_S[(size_t)(col0 + tr) * N + row0 + seg]);
#pragma unroll
        for (int k = 0; k < 8; k++) dst[k] = src[k];
    }
}

// ---------------- kernel 3: per-row loss (partials + vectorized pos CE) -----
__global__ void __launch_bounds__(256) k_rowloss(int N)
{
    __shared__ float redf[8];
    __shared__ float sL;

    const int i = blockIdx.x;
    const int tid = threadIdx.x;

    const int b1 = g_bnd[1];
    const int b2 = g_bnd[2];
    const int NV = g_bnd[3];

    if (i >= NV) {
        if (tid == 0) { g_rowloss[i] = 0.f; g_rowflag[i] = 0; }
        return;
    }

    const int lo = (i < b1) ? 0  : ((i < b2) ? b1 : b2);
    const int hi = (i < b1) ? b1 : ((i < b2) ? b2 : NV);
    const int P  = hi - lo - 1;
    const int ntv = (NV + 127) >> 7;

    // negsum from precomputed tile partials (fixed order)
    float ns = (tid < ntv) ? g_negpart[(size_t)i * 64 + tid] : 0.f;
    ns = wred_f(ns);
    if ((tid & 31) == 0) redf[tid >> 5] = ns;
    __syncthreads();
    if (tid == 0) {
        float tt = 0.f;
#pragma unroll
        for (int w = 0; w < 8; w++) tt += redf[w];
        sL = (tt > 0.f) ? (__logf(tt) + 10.f) : -1e30f;
    }
    __syncthreads();
    const float L = sL;

    if (L <= -1e29f) {                  // no negatives: not processed
        if (tid == 0) { g_rowloss[i] = 0.f; g_rowflag[i] = 0; }
        return;
    }
    if (P == 0) {                       // no positives: pos logit = 1/T = 10
        if (tid == 0) {
            float d = L - 10.f;
            float loss = (d > 0.f) ? d + log1pf(__expf(-d)) : log1pf(__expf(d));
            g_rowloss[i] = loss;
            g_rowflag[i] = 0;
        }
        return;
    }

    // pass 2: psum over positives [lo, hi) \ {i}, vectorized 8-wide
    const __half* __restrict__ row = g_S + (size_t)i * N;
    const uint4* __restrict__ rv = reinterpret_cast<const uint4*>(row);

    float psum = 0.f;
    const int v0 = lo >> 3;
    const int v1 = (hi + 7) >> 3;
    for (int v = v0 + tid; v < v1; v += 256) {
        uint4 w = rv[v];
        const int j0 = v << 3;
        float s[8];
        {
            float2 f;
            f = __half22float2(*reinterpret_cast<__half2*>(&w.x)); s[0] = f.x; s[1] = f.y;
            f = __half22float2(*reinterpret_cast<__half2*>(&w.y)); s[2] = f.x; s[3] = f.y;
            f = __half22float2(*reinterpret_cast<__half2*>(&w.z)); s[4] = f.x; s[5] = f.y;
            f = __half22float2(*reinterpret_cast<__half2*>(&w.w)); s[6] = f.x; s[7] = f.y;
        }
#pragma unroll
        for (int k = 0; k < 8; k++) {
            const int j = j0 + k;
            const bool m = (j >= lo) && (j < hi) && (j != i);
            const float tv = log1pf(__expf(L - s[k]));
            psum += m ? tv : 0.f;
        }
    }
    psum = wred_f(psum);
    if ((tid & 31) == 0) redf[tid >> 5] = psum;
    __syncthreads();
    if (tid == 0) {
        float tt = 0.f;
#pragma unroll
        for (int w = 0; w < 8; w++) tt += redf[w];
        g_rowloss[i] = tt / (float)P;
        g_rowflag[i] = 1;
    }
}

// ---------------- kernel 4: final deterministic reduction -------------------
__global__ void __launch_bounds__(256) k_finalize(float* __restrict__ out, int N)
{
    const int tid = threadIdx.x;
    const float4* rl = reinterpret_cast<const float4*>(g_rowloss);
    const int4*   fl = reinterpret_cast<const int4*>(g_rowflag);
    float s = 0.f;
    int c = 0;
    for (int v = tid; v < N / 4; v += 256) {
        float4 a = rl[v];
        int4   b = fl[v];
        s += a.x + a.y + a.z + a.w;
        c += b.x + b.y + b.z + b.w;
    }
    s = wred_f(s);
    c = wred_i(c);
    __shared__ float redf[8];
    __shared__ int   redi[8];
    if ((tid & 31) == 0) { redf[tid >> 5] = s; redi[tid >> 5] = c; }
    __syncthreads();
    if (tid == 0) {
        float tt = 0.f; int p = 0;
#pragma unroll
        for (int w = 0; w < 8; w++) { tt += redf[w]; p += redi[w]; }
        out[0] = tt / (float)(1 + p);
    }
}

// ---------------- launcher ---------------------------------------------------
extern "C" void kernel_launch(void* const* d_in, const int* in_sizes, int n_in,
                              void* d_out, int out_size)
{
    const float* feats  = (const float*)d_in[0];
    const int*   labels = (const int*)d_in[1];
    const int*   bad    = (const int*)d_in[2];
    float* out = (float*)d_out;

    const int N = in_sizes[1];            // 8192
    const int D = in_sizes[0] / N;        // 512

    k_perm<<<1, 1024>>>(labels, bad, N);
    k_normalize<<<N, 128>>>(feats, N, D);

    const int ntiles = (NTILE * (NTILE + 1)) / 2;   // 2080 (most exit early)
    k_gemm_f16<<<ntiles, 256>>>(N, D);

    k_rowloss<<<N, 256>>>(N);
    k_finalize<<<1, 256>>>(out, N);
}